// round 16
// baseline (speedup 1.0000x reference)
#include <cuda_runtime.h>
#include <cuda_bf16.h>
#include <math.h>
#include <stdint.h>

#define BB 2
#define CY 96
#define CS 48
#define NN 4096
#define QSC 0.20822193f  /* 48^-0.5 * log2(e) */

// ---------------- scratch ----------------------------------------------------
__device__ __align__(16) __nv_bfloat16 g_Qh[BB*NN*CS];
__device__ __align__(16) __nv_bfloat16 g_Kh[BB*NN*CS];
__device__ __align__(16) __nv_bfloat16 g_Vth[BB*CS*NN];   // V transposed, unnormalized
__device__ __align__(16) float g_psum[BB*8*NN];
__device__ __align__(16) float g_iz[BB*NN];
__device__ __align__(16) float g_Xp[8*BB*NN*CS];
__device__ __align__(16) float g_Y3p[6*BB*CY*NN];         // 6 conv partials
__device__ __align__(16) float g_peS[CS*256];
__device__ __align__(16) float g_peY[CY*256];
// conv implicit-GEMM operands
__device__ __align__(16) __nv_bfloat16 g_Ypadh[BB*18*324*96];  // zero halo stays zero
__device__ __align__(16) __nv_bfloat16 g_Ypadl[BB*18*324*96];
__device__ __align__(16) __nv_bfloat16 g_w3h[27*96*96], g_w3l[27*96*96];

// ---------------- helpers ----------------------------------------------------
__device__ __forceinline__ void mma16816(float* c, const uint32_t* a, const uint32_t* b) {
    asm volatile(
        "mma.sync.aligned.m16n8k16.row.col.f32.bf16.bf16.f32 "
        "{%0,%1,%2,%3}, {%4,%5,%6,%7}, {%8,%9}, {%0,%1,%2,%3};\n"
        : "+f"(c[0]), "+f"(c[1]), "+f"(c[2]), "+f"(c[3])
        : "r"(a[0]), "r"(a[1]), "r"(a[2]), "r"(a[3]), "r"(b[0]), "r"(b[1]));
}
__device__ __forceinline__ uint32_t bf2u(__nv_bfloat16 a, __nv_bfloat16 b) {
    __nv_bfloat162 v(a, b);
    return *reinterpret_cast<uint32_t*>(&v);
}
__device__ __forceinline__ uint32_t cvt2bf(float lo, float hi) {
    uint32_t r;
    asm("cvt.rn.bf16x2.f32 %0, %1, %2;" : "=r"(r) : "f"(hi), "f"(lo));
    return r;
}
__device__ __forceinline__ void cpa16(const void* smem, const void* gmem) {
    uint32_t s = (uint32_t)__cvta_generic_to_shared(smem);
    asm volatile("cp.async.cg.shared.global [%0], [%1], 16;\n" :: "r"(s), "l"(gmem));
}
#define CPA_COMMIT() asm volatile("cp.async.commit_group;\n" ::: "memory")
#define CPA_WAIT(N)  asm volatile("cp.async.wait_group %0;\n" :: "n"(N) : "memory")
__device__ __forceinline__ void ldsm4(uint32_t* r, uint32_t saddr) {
    asm volatile("ldmatrix.sync.aligned.m8n8.x4.shared.b16 {%0,%1,%2,%3}, [%4];"
        : "=r"(r[0]), "=r"(r[1]), "=r"(r[2]), "=r"(r[3]) : "r"(saddr));
}

// ---------------- PE tables --------------------------------------------------
__device__ __forceinline__ float pe_val(int ch, int h, int w, int c) {
    int blk = ch / c, t = ch - blk * c;
    int pos = (blk < 2) ? h : w;    // torch broadcast quirk
    int half = c >> 1;
    if (t < half) {
        float invf = powf(10000.f, -2.f * (float)t / (float)c);
        return sinf((float)pos * invf);
    } else {
        float invf = powf(10000.f, -2.f * (float)(t - half) / (float)c);
        return cosf((float)pos * invf);
    }
}
__global__ void k_petab() {
    int i = blockIdx.x * 256 + threadIdx.x;
    if (i < CY * 256) {
        int ch = i >> 8, n = i & 255;
        g_peY[i] = pe_val(ch, n >> 4, n & 15, 32);
    } else {
        int j = i - CY * 256;
        if (j < CS * 256) {
            int ch = j >> 8, n = j & 255;
            g_peS[j] = pe_val(ch, n >> 4, n & 15, 16);
        }
    }
}

// ---------------- weight prep: w3[co][ci][tap] -> bf16 h/l [tap][co][ci] ----
__global__ void k_wprep(const float* __restrict__ w3) {
    int j = blockIdx.x * 256 + threadIdx.x;
    if (j >= 27 * 96 * 96) return;
    int ci = j % 96, co = (j / 96) % 96, tap = j / 9216;
    float v = w3[(co * 96 + ci) * 27 + tap];
    __nv_bfloat16 h = __float2bfloat16(v);
    g_w3h[j] = h;
    g_w3l[j] = __float2bfloat16(v - __bfloat162float(h));
}

// ============================================================================
// PROJ: [0,128) proj_sv -> Vt bf16 | [128,256) proj_y1+QK
// ============================================================================
#define PROJ_SMEM 55552
__global__ __launch_bounds__(256) void k_proj(
    const float* __restrict__ Y, const float* __restrict__ S,
    const float* __restrict__ w_s, const float* __restrict__ b_s,
    const float* __restrict__ g_s, const float* __restrict__ be_s,
    const float* __restrict__ Wv,
    const float* __restrict__ w_y, const float* __restrict__ b_y,
    const float* __restrict__ g_y, const float* __restrict__ be_y,
    const float* __restrict__ Wq, const float* __restrict__ Wk)
{
    extern __shared__ __align__(16) float pool[];
    int bx = blockIdx.x, t = threadIdx.x;

    if (bx < 128) {
        int n0 = (bx & 63) * 64, b = bx >> 6;
        float* in_s = pool;            // [48][64], later reused as Vt staging
        float* wt   = pool + 3072;
        float* wv   = pool + 5376;
        float* s1   = pool + 7680;

        for (int i = t; i < CS * CS; i += 256) {
            int e = i % CS, c = i / CS;
            wt[i] = w_s[e * CS + c];
            wv[i] = Wv[i];
        }
        for (int i = t; i < CS * 64; i += 256) {
            int c = i >> 6, nl = i & 63;
            in_s[i] = S[(b * CS + c) * NN + n0 + nl]
                    + g_peS[c * 256 + ((n0 + nl) & 255)];
        }
        __syncthreads();

        int n = t & 63, eg = t >> 6;
        float acc[12];
#pragma unroll
        for (int k = 0; k < 12; k++) acc[k] = 0.f;
        for (int c = 0; c < CS; c++) {
            float x = in_s[c * 64 + n];
#pragma unroll
            for (int v = 0; v < 3; v++) {
                float4 w4 = *(const float4*)&wt[c * CS + eg * 12 + v * 4];
                acc[v*4+0] += w4.x * x; acc[v*4+1] += w4.y * x;
                acc[v*4+2] += w4.z * x; acc[v*4+3] += w4.w * x;
            }
        }
        float inv = rsqrtf(1.f + 1e-5f);
#pragma unroll
        for (int k = 0; k < 12; k++) {
            int e = eg * 12 + k;
            float y = (acc[k] + b_s[e]) * (g_s[e] * inv) + be_s[e];
            s1[n * 49 + e] = fmaxf(y, 0.f);
        }
        __syncthreads();

#pragma unroll
        for (int k = 0; k < 12; k++) acc[k] = 0.f;
        for (int d = 0; d < CS; d++) {
            float x = s1[n * 49 + d];
#pragma unroll
            for (int v = 0; v < 3; v++) {
                float4 w4 = *(const float4*)&wv[d * CS + eg * 12 + v * 4];
                acc[v*4+0] += w4.x * x; acc[v*4+1] += w4.y * x;
                acc[v*4+2] += w4.z * x; acc[v*4+3] += w4.w * x;
            }
        }
        // transpose V into in_s[d][n], then emit bf16 transposed global
        __syncthreads();           // everyone done reading in_s (inputs)
#pragma unroll
        for (int k = 0; k < 12; k++)
            in_s[(eg * 12 + k) * 64 + n] = acc[k];
        __syncthreads();
        for (int i = t; i < CS * 64; i += 256) {
            int d = i >> 6, nl = i & 63;
            g_Vth[(size_t)(b * CS + d) * NN + n0 + nl] = __float2bfloat16(in_s[i]);
        }
        return;
    }

    {   // proj_y1 + QK fused; Y1 lives only in smem. Q pre-scaled by QSC.
        int j = bx - 128;
        int n0 = (j & 63) * 64, b = j >> 6;
        float* in_s = pool;            // [96][64]
        float* wt   = pool + 6144;     // [c][e]
        float* s1   = pool + 10752;    // [n][49]

        for (int i = t; i < CY * CS; i += 256) {
            int e = i % CS, c = i / CS;
            wt[i] = w_y[e * CY + c];
        }
        for (int i = t; i < CY * 64; i += 256) {
            int c = i >> 6, nl = i & 63;
            in_s[i] = Y[(b * CY + c) * NN + n0 + nl]
                    + g_peY[c * 256 + ((n0 + nl) & 255)];
        }
        __syncthreads();

        int n = t & 63, eg = t >> 6;
        float acc[12];
#pragma unroll
        for (int k = 0; k < 12; k++) acc[k] = 0.f;
        for (int c = 0; c < CY; c++) {
            float x = in_s[c * 64 + n];
#pragma unroll
            for (int v = 0; v < 3; v++) {
                float4 w4 = *(const float4*)&wt[c * CS + eg * 12 + v * 4];
                acc[v*4+0] += w4.x * x; acc[v*4+1] += w4.y * x;
                acc[v*4+2] += w4.z * x; acc[v*4+3] += w4.w * x;
            }
        }
        float inv = rsqrtf(1.f + 1e-5f);
#pragma unroll
        for (int k = 0; k < 12; k++) {
            int e = eg * 12 + k;
            float y = (acc[k] + b_y[e]) * (g_y[e] * inv) + be_y[e];
            s1[n * 49 + e] = fmaxf(y, 0.f);
        }
        __syncthreads();

        float* wq = pool;
        float* wk = pool + 2304;
        for (int i = t; i < CS * CS; i += 256) { wq[i] = Wq[i]; wk[i] = Wk[i]; }
        __syncthreads();

        float aq[12], ak[12];
#pragma unroll
        for (int k = 0; k < 12; k++) { aq[k] = 0.f; ak[k] = 0.f; }
        for (int d = 0; d < CS; d++) {
            float x = s1[n * 49 + d];
#pragma unroll
            for (int v = 0; v < 3; v++) {
                float4 q4 = *(const float4*)&wq[d * CS + eg * 12 + v * 4];
                float4 k4 = *(const float4*)&wk[d * CS + eg * 12 + v * 4];
                aq[v*4+0] += q4.x * x; aq[v*4+1] += q4.y * x;
                aq[v*4+2] += q4.z * x; aq[v*4+3] += q4.w * x;
                ak[v*4+0] += k4.x * x; ak[v*4+1] += k4.y * x;
                ak[v*4+2] += k4.z * x; ak[v*4+3] += k4.w * x;
            }
        }
        int base = (b * NN + n0 + n) * CS + eg * 12;
#pragma unroll
        for (int k = 0; k < 12; k++) {
            g_Qh[base + k] = __float2bfloat16(aq[k] * QSC);
            g_Kh[base + k] = __float2bfloat16(ak[k]);
        }
    }
}

// ---------------- input prep: (Y + peY) -> channel-last padded bf16 h/l -----
__global__ __launch_bounds__(256) void k_ytrans(const float* __restrict__ Y) {
    int z = blockIdx.x, half = blockIdx.y, b = blockIdx.z, t = threadIdx.x;
    int y = t >> 4, x = t & 15;
    size_t dstbase = (((size_t)(b * 18 + z + 1) * 324) + (y + 1) * 18 + (x + 1)) * 96;
    uint32_t hp[24], lp[24];
#pragma unroll
    for (int c2 = 0; c2 < 24; c2++) {
        int ci = half * 48 + c2 * 2;
        float v0 = Y[(size_t)(b * CY + ci) * NN + z * 256 + t] + g_peY[ci * 256 + t];
        float v1 = Y[(size_t)(b * CY + ci + 1) * NN + z * 256 + t] + g_peY[(ci + 1) * 256 + t];
        __nv_bfloat16 h0 = __float2bfloat16(v0), h1 = __float2bfloat16(v1);
        hp[c2] = bf2u(h0, h1);
        lp[c2] = bf2u(__float2bfloat16(v0 - __bfloat162float(h0)),
                      __float2bfloat16(v1 - __bfloat162float(h1)));
    }
    uint4* dh = (uint4*)(g_Ypadh + dstbase + half * 48);
    uint4* dl = (uint4*)(g_Ypadl + dstbase + half * 48);
#pragma unroll
    for (int q = 0; q < 6; q++) {
        dh[q] = make_uint4(hp[q*4], hp[q*4+1], hp[q*4+2], hp[q*4+3]);
        dl[q] = make_uint4(lp[q*4], lp[q*4+1], lp[q*4+2], lp[q*4+3]);
    }
}

// ============================================================================
// Pass 1: column sums. A = K-tile persistent frags, B = Q chunks of 64.
// grid (32, 8, BB). smem 28672 B.
// ============================================================================
#define CS_SMEM 28672
__global__ __launch_bounds__(256) void k_colsum() {
    extern __shared__ __align__(16) unsigned char dsm[];
    __nv_bfloat16* KH = (__nv_bfloat16*)dsm;          // [128][56]
    __nv_bfloat16* QB = KH + 7168;                    // 2 bufs x QH[64][56]

    int k0 = blockIdx.x * 128, qq = blockIdx.y, b = blockIdx.z;
    int t = threadIdx.x, wid = t >> 5, l = t & 31;
    int lr = l >> 2, lc = (l & 3) * 2;
    int mb = wid * 16;

    {
        const __nv_bfloat16* s = g_Kh + (size_t)(b * NN + k0) * CS;
        for (int i = t; i < 768; i += 256) {
            int r = i / 6, c = i % 6;
            *(uint4*)(KH + r * 56 + c * 8) = *(const uint4*)(s + r * 48 + c * 8);
        }
    }
    __syncthreads();

    uint32_t kfh[3][4];
#pragma unroll
    for (int ks = 0; ks < 3; ks++) {
        int ko = ks * 16;
        kfh[ks][0] = *(uint32_t*)&KH[(mb + lr) * 56 + ko + lc];
        kfh[ks][1] = *(uint32_t*)&KH[(mb + 8 + lr) * 56 + ko + lc];
        kfh[ks][2] = *(uint32_t*)&KH[(mb + lr) * 56 + ko + lc + 8];
        kfh[ks][3] = *(uint32_t*)&KH[(mb + 8 + lr) * 56 + ko + lc + 8];
    }

    int lg = l >> 3, lrow = l & 7;
    int rowext = ((lg & 2) ? 8 : 0) + lrow;
    int colext = (lg & 1) ? 8 : 0;

    auto prefetchQ = [&](int ch, int bi) {
        int qb = qq * 512 + ch * 64;
        __nv_bfloat16* QH = QB + bi * 3584;
        const __nv_bfloat16* sh = g_Qh + (size_t)(b * NN + qb) * CS;
        for (int i = t; i < 384; i += 256) {
            int r = i / 6, c = i % 6;
            cpa16(QH + r * 56 + c * 8, sh + r * 48 + c * 8);
        }
        CPA_COMMIT();
    };

    float rs0 = 0.f, rs1 = 0.f;
    prefetchQ(0, 0);
    for (int ch = 0; ch < 8; ch++) {
        if (ch < 7) prefetchQ(ch + 1, (ch + 1) & 1);
        if (ch < 7) { CPA_WAIT(1); } else { CPA_WAIT(0); }
        __syncthreads();
        __nv_bfloat16* QH = QB + (ch & 1) * 3584;
        uint32_t qbase = (uint32_t)__cvta_generic_to_shared(QH);

#pragma unroll
        for (int nfp = 0; nfp < 4; nfp++) {
            float a0[4] = {0.f,0.f,0.f,0.f}, a1[4] = {0.f,0.f,0.f,0.f};
#pragma unroll
            for (int ks = 0; ks < 3; ks++) {
                int ko = ks * 16;
                uint32_t bf[4];
                ldsm4(bf, qbase + ((nfp * 16 + rowext) * 56 + ko + colext) * 2);
                mma16816(a0, kfh[ks], bf);
                mma16816(a1, kfh[ks], bf + 2);
            }
            rs0 += exp2f(a0[0]) + exp2f(a0[1]) + exp2f(a1[0]) + exp2f(a1[1]);
            rs1 += exp2f(a0[2]) + exp2f(a0[3]) + exp2f(a1[2]) + exp2f(a1[3]);
        }
        __syncthreads();
    }
    rs0 += __shfl_xor_sync(0xffffffffu, rs0, 1);
    rs0 += __shfl_xor_sync(0xffffffffu, rs0, 2);
    rs1 += __shfl_xor_sync(0xffffffffu, rs1, 1);
    rs1 += __shfl_xor_sync(0xffffffffu, rs1, 2);
    if ((l & 3) == 0) {
        g_psum[(b * 8 + qq) * NN + k0 + mb + lr]     = rs0;
        g_psum[(b * 8 + qq) * NN + k0 + mb + 8 + lr] = rs1;
    }
}

// ---------------- iz: 1 / (sum of 8 psum partials) --------------------------
__global__ void k_iz() {
    int k = blockIdx.x * 256 + threadIdx.x, b = blockIdx.y;
    float s = 0.f;
#pragma unroll
    for (int i = 0; i < 8; i++) s += g_psum[(b * 8 + i) * NN + k];
    g_iz[b * NN + k] = 1.f / s;
}

// ============================================================================
// flash pass2: QK recompute -> exp2 * iz[k] -> P as A-frags into 1-term P @ V.
// grid (32, 8, BB). smem 28672 B.
// ============================================================================
#define FLASH_SMEM 28672
__global__ __launch_bounds__(256) void k_flash() {
    extern __shared__ __align__(16) unsigned char dsm[];
    __nv_bfloat16* base = (__nv_bfloat16*)dsm;
    __nv_bfloat16* KB = base;                 // 2 bufs x KH[64][56]; overlaps Q staging
    __nv_bfloat16* VB = base + 7168;          // 2 bufs x VH[48][72]
    float* IZB = (float*)(base + 14080);      // 2 bufs x 64 floats

    int qblk = blockIdx.x, kq = blockIdx.y, b = blockIdx.z;
    int t = threadIdx.x, wid = t >> 5, l = t & 31;
    int lr = l >> 2, lc = (l & 3) * 2;
    int q0 = qblk * 128, mb = wid * 16;

    {
        __nv_bfloat16* QH = base;
        const __nv_bfloat16* s = g_Qh + (size_t)(b * NN + q0) * CS;
        for (int i = t; i < 768; i += 256) {
            int r = i / 6, c = i % 6;
            *(uint4*)(QH + r * 56 + c * 8) = *(const uint4*)(s + r * 48 + c * 8);
        }
    }
    __syncthreads();

    uint32_t qfh[3][4];
    {
        __nv_bfloat16* QH = base;
#pragma unroll
        for (int ks = 0; ks < 3; ks++) {
            int ko = ks * 16;
            qfh[ks][0] = *(uint32_t*)&QH[(mb + lr) * 56 + ko + lc];
            qfh[ks][1] = *(uint32_t*)&QH[(mb + 8 + lr) * 56 + ko + lc];
            qfh[ks][2] = *(uint32_t*)&QH[(mb + lr) * 56 + ko + lc + 8];
            qfh[ks][3] = *(uint32_t*)&QH[(mb + 8 + lr) * 56 + ko + lc + 8];
        }
    }
    __syncthreads();   // frag extraction done before K bufs overwrite Q region

    int lg = l >> 3, lrow = l & 7;
    int rowext = ((lg & 2) ? 8 : 0) + lrow;
    int colext = (lg & 1) ? 8 : 0;

    auto prefetchKV = [&](int ch, int bi) {
        int kb = kq * 512 + ch * 64;
        __nv_bfloat16* KHc = KB + bi * 3584;
        __nv_bfloat16* VHc = VB + bi * 3456;
        const __nv_bfloat16* skh = g_Kh + (size_t)(b * NN + kb) * CS;
        for (int i = t; i < 384; i += 256) {
            int r = i / 6, c = i % 6;
            cpa16(KHc + r * 56 + c * 8, skh + r * 48 + c * 8);
        }
        const __nv_bfloat16* svh = g_Vth + (size_t)(b * CS) * NN + kb;
        for (int i = t; i < 384; i += 256) {
            int r = i / 8, c = i % 8;
            cpa16(VHc + r * 72 + c * 8, svh + (size_t)r * NN + c * 8);
        }
        if (t < 16)
            cpa16(IZB + bi * 64 + t * 4, g_iz + b * NN + kb + t * 4);
        CPA_COMMIT();
    };

    float pv[6][4];
#pragma unroll
    for (int nv = 0; nv < 6; nv++)
#pragma unroll
        for (int c = 0; c < 4; c++) pv[nv][c] = 0.f;

    prefetchKV(0, 0);
    for (int ch = 0; ch < 8; ch++) {
        if (ch < 7) prefetchKV(ch + 1, (ch + 1) & 1);
        if (ch < 7) { CPA_WAIT(1); } else { CPA_WAIT(0); }
        __syncthreads();
        __nv_bfloat16* KHc = KB + (ch & 1) * 3584;
        __nv_bfloat16* VHc = VB + (ch & 1) * 3456;
        const float* IZc = IZB + (ch & 1) * 64;
        uint32_t kbase = (uint32_t)__cvta_generic_to_shared(KHc);
        uint32_t vhb   = (uint32_t)__cvta_generic_to_shared(VHc);

#pragma unroll
        for (int nfp = 0; nfp < 4; nfp++) {
            float a0[4] = {0.f,0.f,0.f,0.f}, a1[4] = {0.f,0.f,0.f,0.f};
#pragma unroll
            for (int ks = 0; ks < 3; ks++) {
                int ko = ks * 16;
                uint32_t bf[4];
                ldsm4(bf, kbase + ((nfp * 16 + rowext) * 56 + ko + colext) * 2);
                mma16816(a0, qfh[ks], bf);
                mma16816(a1, qfh[ks], bf + 2);
            }
            int kop = nfp * 16;
            float z0 = IZc[kop + lc],     z1 = IZc[kop + lc + 1];
            float z2 = IZc[kop + 8 + lc], z3 = IZc[kop + 8 + lc + 1];
            uint32_t ph[4];
            ph[0] = cvt2bf(exp2f(a0[0]) * z0, exp2f(a0[1]) * z1);
            ph[1] = cvt2bf(exp2f(a0[2]) * z0, exp2f(a0[3]) * z1);
            ph[2] = cvt2bf(exp2f(a1[0]) * z2, exp2f(a1[1]) * z3);
            ph[3] = cvt2bf(exp2f(a1[2]) * z2, exp2f(a1[3]) * z3);
#pragma unroll
            for (int p2 = 0; p2 < 3; p2++) {
                uint32_t vh[4];
                uint32_t off = ((p2 * 16 + rowext) * 72 + kop + colext) * 2;
                ldsm4(vh, vhb + off);
                mma16816(pv[2*p2],     ph, vh);
                mma16816(pv[2*p2 + 1], ph, vh + 2);
            }
        }
        __syncthreads();
    }

#pragma unroll
    for (int nv = 0; nv < 6; nv++) {
        int r = q0 + mb + lr, col = nv * 8 + lc;
        float* basep = &g_Xp[((size_t)(kq * BB + b) * NN + r) * CS + col];
        *(float2*)basep = make_float2(pv[nv][0], pv[nv][1]);
        *(float2*)(basep + 8 * CS) = make_float2(pv[nv][2], pv[nv][3]);
    }
}

// ============================================================================
// conv3d implicit GEMM, 3-term bf16, y-split 2x + forced occ 2.
// grid (32 = z*2+yh, 6 = dz*2+cihalf, BB). slab 180 rows x 48 ci (34.5 KB).
// ============================================================================
#define CONV_SMEM 34560
__global__ __launch_bounds__(256, 2) void k_conv() {
    extern __shared__ __align__(16) unsigned char dsm[];
    __nv_bfloat16* SH = (__nv_bfloat16*)dsm;      // [180][48] hi
    __nv_bfloat16* SL = SH + 180 * 48;            // [180][48] lo

    int z = blockIdx.x >> 1, yh = blockIdx.x & 1;
    int s = blockIdx.y, b = blockIdx.z;
    int dz = s >> 1, half = s & 1;
    int t = threadIdx.x, wid = t >> 5, l = t & 31;
    int wm = wid >> 2, wn = wid & 3;              // 2 m-warps x 4 n-warps (n=128)
    int lg = l >> 3, lrow = l & 7;
    int rowext = ((lg & 2) ? 8 : 0) + lrow;
    int colext = (lg & 1) ? 8 : 0;

    // stage 180 contiguous padded rows starting at yh*144
    {
        const __nv_bfloat16* srch = g_Ypadh
            + ((size_t)(b * 18 + z + dz) * 324 + yh * 144) * 96 + half * 48;
        const __nv_bfloat16* srcl = g_Ypadl
            + ((size_t)(b * 18 + z + dz) * 324 + yh * 144) * 96 + half * 48;
        for (int i = t; i < 180 * 6; i += 256) {
            int r = i / 6, c = i % 6;
            cpa16(SH + r * 48 + c * 8, srch + (size_t)r * 96 + c * 8);
            cpa16(SL + r * 48 + c * 8, srcl + (size_t)r * 96 + c * 8);
        }
        CPA_COMMIT(); CPA_WAIT(0);
    }
    __syncthreads();

    int py[2], px[2];
#pragma unroll
    for (int pair = 0; pair < 2; pair++) {
        int nl = wn * 32 + pair * 16 + rowext;
        py[pair] = nl >> 4;
        px[pair] = nl & 15;
    }
    uint32_t sbh = (uint32_t)__cvta_generic_to_shared(SH);
    uint32_t sbl = (uint32_t)__cvta_generic_to_shared(SL);

    float acc[3][4][4];
#pragma unroll
    for (int mf = 0; mf < 3; mf++)
#pragma unroll
        for (int nf = 0; nf < 4; nf++)
#pragma unroll
            for (int c = 0; c < 4; c++) acc[mf][nf][c] = 0.f;

    int arow = l >> 2, acol = (l & 3) * 2;

    for (int tap = 0; tap < 9; tap++) {
        int dy = tap / 3, dx = tap % 3;
        int tapg = dz * 9 + tap;
#pragma unroll
        for (int ks = 0; ks < 3; ks++) {
            uint32_t ah[3][4], al[3][4];
#pragma unroll
            for (int mf = 0; mf < 3; mf++) {
                size_t aoff = (size_t)tapg * 9216
                            + (size_t)(wm * 48 + mf * 16 + arow) * 96
                            + half * 48 + ks * 16 + acol;
                const __nv_bfloat16* ph = g_w3h + aoff;
                ah[mf][0] = *(const uint32_t*)ph;
                ah[mf][1] = *(const uint32_t*)(ph + 8 * 96);
                ah[mf][2] = *(const uint32_t*)(ph + 8);
                ah[mf][3] = *(const uint32_t*)(ph + 8 * 96 + 8);
                const __nv_bfloat16* pl = g_w3l + aoff;
                al[mf][0] = *(const uint32_t*)pl;
                al[mf][1] = *(const uint32_t*)(pl + 8 * 96);
                al[mf][2] = *(const uint32_t*)(pl + 8);
                al[mf][3] = *(const uint32_t*)(pl + 8 * 96 + 8);
            }
            uint32_t bh[2][4], bl[2][4];
#pragma unroll
            for (int pair = 0; pair < 2; pair++) {
                int srow = (py[pair] + dy) * 18 + px[pair] + dx;
                uint32_t off = (uint32_t)(srow * 48 + ks * 16 + colext) * 2;
                ldsm4(bh[pair], sbh + off);
                ldsm4(bl[pair], sbl + off);
            }
#pragma unroll
            for (int mf = 0; mf < 3; mf++)
#pragma unroll
                for (int pair = 0; pair < 2; pair++) {
                    mma16816(acc[mf][2*pair],     ah[mf], bh[pair]);
                    mma16816(acc[mf][2*pair],     al[mf], bh[pair]);
                    mma16816(acc[mf][2*pair],     ah[mf], bl[pair]);
                    mma16816(acc[mf][2*pair + 1], ah[mf], bh[pair] + 2);
                    mma16816(acc[mf][2*pair + 1], al[mf], bh[pair] + 2);
                    mma16816(acc[mf][2*pair + 1], ah[mf], bl[pair] + 2);
                }
        }
    }

    float* out = g_Y3p + (size_t)s * (BB * CY * NN) + (size_t)(b * CY) * NN
               + z * 256 + yh * 128;
#pragma unroll
    for (int mf = 0; mf < 3; mf++) {
        int r0 = wm * 48 + mf * 16 + (l >> 2);
#pragma unroll
        for (int nf = 0; nf < 4; nf++) {
            int c = wn * 32 + nf * 8 + (l & 3) * 2;
            *(float2*)&out[(size_t)r0 * NN + c]       = make_float2(acc[mf][nf][0], acc[mf][nf][1]);
            *(float2*)&out[(size_t)(r0 + 8) * NN + c] = make_float2(acc[mf][nf][2], acc[mf][nf][3]);
        }
    }
}

// ============================================================================
// FUSE2: [0,128) zout | [128,256) y2out (sums 6 conv partials)
// ============================================================================
#define FUSE2_SMEM 43008
__global__ __launch_bounds__(256) void k_fuse2(
    const float* __restrict__ S,
    const float* __restrict__ w_o, const float* __restrict__ b_o,
    const float* __restrict__ g_o, const float* __restrict__ be_o,
    const float* __restrict__ w_y2, const float* __restrict__ b_y2,
    const float* __restrict__ g_y2, const float* __restrict__ be_y2,
    const float* __restrict__ b3, float* __restrict__ out)
{
    extern __shared__ __align__(16) float pool[];
    int bx = blockIdx.x, t = threadIdx.x;

    if (bx < 128) {
        int n0 = (bx & 63) * 64, b = bx >> 6;
        float* xs  = pool;
        float* wot = pool + 3072;

        for (int i = t; i < CS * CS; i += 256) {
            int e = i % CS, d = i / CS;
            wot[i] = w_o[e * CS + d];
        }
        {
            int n = t & 63, v = t >> 6;
            const size_t cstride = (size_t)BB * NN * CS;
            const float* src = g_Xp + (size_t)(b * NN + n0 + n) * CS;
#pragma unroll
            for (int r = 0; r < 3; r++) {
                int dv = v + r * 4;
                float4 x = *(const float4*)&src[dv * 4];
#pragma unroll
                for (int p = 1; p < 8; p++) {
                    float4 xp = *(const float4*)&src[p * cstride + dv * 4];
                    x.x += xp.x; x.y += xp.y; x.z += xp.z; x.w += xp.w;
                }
                xs[(dv*4+0)*64+n] = x.x; xs[(dv*4+1)*64+n] = x.y;
                xs[(dv*4+2)*64+n] = x.z; xs[(dv*4+3)*64+n] = x.w;
            }
        }
        __syncthreads();

        int n = t & 63, eg = t >> 6;
        float acc[12];
#pragma unroll
        for (int k = 0; k < 12; k++) acc[k] = 0.f;
        for (int d = 0; d < CS; d++) {
            float x = xs[d * 64 + n];
#pragma unroll
            for (int v = 0; v < 3; v++) {
                float4 w4 = *(const float4*)&wot[d * CS + eg * 12 + v * 4];
                acc[v*4+0] += w4.x * x; acc[v*4+1] += w4.y * x;
                acc[v*4+2] += w4.z * x; acc[v*4+3] += w4.w * x;
            }
        }
        float inv = rsqrtf(1.f + 1e-5f);
#pragma unroll
        for (int k = 0; k < 12; k++) {
            int e = eg * 12 + k;
            float y = (acc[k] + b_o[e]) * (g_o[e] * inv) + be_o[e];
            y = fmaxf(y, 0.f);
            float spe = S[(b * CS + e) * NN + n0 + n]
                      + g_peS[e * 256 + ((n0 + n) & 255)];
            out[(b * 96 + e) * NN + n0 + n] = y * spe;
        }
        return;
    }

    {
        int j = bx - 128;
        int n0 = (j & 63) * 64, b = j >> 6;
        float* in_s = pool;
        float* wt   = pool + 6144;

        for (int i = t; i < CY * CS; i += 256) {
            int e = i % CS, c = i / CS;
            wt[i] = w_y2[e * CY + c];
        }
        const size_t pstride = (size_t)BB * CY * NN;
        const float* src = g_Y3p + (size_t)(b * CY) * NN + n0;
        for (int i = t; i < CY * 64; i += 256) {
            int c = i >> 6, n = i & 63;
            float v = b3[c];
#pragma unroll
            for (int p = 0; p < 6; p++) v += src[p * pstride + c * NN + n];
            in_s[i] = v;
        }
        __syncthreads();

        int n = t & 63, eg = t >> 6;
        float acc[12];
#pragma unroll
        for (int k = 0; k < 12; k++) acc[k] = 0.f;
        for (int c = 0; c < CY; c++) {
            float x = in_s[c * 64 + n];
#pragma unroll
            for (int v = 0; v < 3; v++) {
                float4 w4 = *(const float4*)&wt[c * CS + eg * 12 + v * 4];
                acc[v*4+0] += w4.x * x; acc[v*4+1] += w4.y * x;
                acc[v*4+2] += w4.z * x; acc[v*4+3] += w4.w * x;
            }
        }
        float inv = rsqrtf(1.f + 1e-5f);
#pragma unroll
        for (int k = 0; k < 12; k++) {
            int e = eg * 12 + k;
            float y = (acc[k] + b_y2[e]) * (g_y2[e] * inv) + be_y2[e];
            out[(b * 96 + 48 + e) * NN + n0 + n] = fmaxf(y, 0.f);
        }
    }
}

// ---------------- launch -----------------------------------------------------
extern "C" void kernel_launch(void* const* d_in, const int* in_sizes, int n_in,
                              void* d_out, int out_size)
{
    const float* Y    = (const float*)d_in[0];
    const float* S    = (const float*)d_in[1];
    const float* w_s  = (const float*)d_in[2];
    const float* b_s  = (const float*)d_in[3];
    const float* g_s  = (const float*)d_in[4];
    const float* be_s = (const float*)d_in[5];
    const float* w_y  = (const float*)d_in[6];
    const float* b_y  = (const float*)d_in[7];
    const float* g_y  = (const float*)d_in[8];
    const float* be_y = (const float*)d_in[9];
    const float* Wq   = (const float*)d_in[10];
    const float* Wk   = (const float*)d_in[11];
    const float* Wv   = (const float*)d_in[12];
    const float* w_o  = (const float*)d_in[13];
    const float* b_o  = (const float*)d_in[14];
    const float* g_o  = (const float*)d_in[15];
    const float* be_o = (const float*)d_in[16];
    const float* w3   = (const float*)d_in[17];
    const float* b3   = (const float*)d_in[18];
    const float* w_y2 = (const float*)d_in[19];
    const float* b_y2 = (const float*)d_in[20];
    const float* g_y2 = (const float*)d_in[21];
    const float* be_y2= (const float*)d_in[22];
    float* out = (float*)d_out;

    static cudaStream_t s2 = nullptr;
    static cudaEvent_t evP = nullptr, ev2 = nullptr;
    static int attr_done = 0;
    if (!attr_done) {
        cudaFuncSetAttribute(k_proj,   cudaFuncAttributeMaxDynamicSharedMemorySize, PROJ_SMEM);
        cudaFuncSetAttribute(k_colsum, cudaFuncAttributeMaxDynamicSharedMemorySize, CS_SMEM);
        cudaFuncSetAttribute(k_flash,  cudaFuncAttributeMaxDynamicSharedMemorySize, FLASH_SMEM);
        cudaFuncSetAttribute(k_conv,   cudaFuncAttributeMaxDynamicSharedMemorySize, CONV_SMEM);
        cudaStreamCreateWithFlags(&s2, cudaStreamNonBlocking);
        cudaEventCreateWithFlags(&evP, cudaEventDisableTiming);
        cudaEventCreateWithFlags(&ev2, cudaEventDisableTiming);
        attr_done = 1;
    }

    // s2: weight prep needs nothing
    k_wprep <<<972, 256, 0, s2>>>(w3);
    // default: PE tables; conv branch forks right after (needs only peY + Y)
    k_petab <<<144, 256>>>();
    cudaEventRecord(evP, 0);
    cudaStreamWaitEvent(s2, evP, 0);
    k_ytrans<<<dim3(16, 2, BB), 256, 0, s2>>>(Y);
    k_conv  <<<dim3(32, 6, BB), 256, CONV_SMEM, s2>>>();
    cudaEventRecord(ev2, s2);

    // attention chain on default
    k_proj  <<<256, 256, PROJ_SMEM>>>(Y, S, w_s, b_s, g_s, be_s, Wv,
                                      w_y, b_y, g_y, be_y, Wq, Wk);
    k_colsum<<<dim3(32, 8, BB), 256, CS_SMEM>>>();
    k_iz    <<<dim3(16, BB), 256>>>();
    k_flash <<<dim3(32, 8, BB), 256, FLASH_SMEM>>>();

    cudaStreamWaitEvent(0, ev2, 0);
    k_fuse2 <<<256, 256, FUSE2_SMEM>>>(S, w_o, b_o, g_o, be_o,
                                       w_y2, b_y2, g_y2, be_y2, b3, out);
}

// round 17
// speedup vs baseline: 1.1519x; 1.1519x over previous
#include <cuda_runtime.h>
#include <cuda_bf16.h>
#include <math.h>
#include <stdint.h>

#define BB 2
#define CY 96
#define CS 48
#define NN 4096
#define QSC 0.20822193f  /* 48^-0.5 * log2(e) */

// ---------------- scratch ----------------------------------------------------
__device__ __align__(16) __nv_bfloat16 g_Qh[BB*NN*CS];
__device__ __align__(16) __nv_bfloat16 g_Kh[BB*NN*CS];
__device__ __align__(16) __nv_bfloat16 g_Vth[BB*CS*NN];   // V transposed, unnormalized
__device__ __align__(16) float g_psum[BB*8*NN];
__device__ __align__(16) float g_iz[BB*NN];
__device__ __align__(16) float g_Xp[8*BB*NN*CS];
__device__ __align__(16) float g_Y3p[6*BB*CY*NN];         // 6 conv partials
__device__ __align__(16) float g_peS[CS*256];
__device__ __align__(16) float g_peY[CY*256];
// conv implicit-GEMM operands
__device__ __align__(16) __nv_bfloat16 g_Ypadh[BB*18*324*96];  // zero halo stays zero
__device__ __align__(16) __nv_bfloat16 g_Ypadl[BB*18*324*96];
__device__ __align__(16) __nv_bfloat16 g_w3h[27*96*96], g_w3l[27*96*96];

// ---------------- helpers ----------------------------------------------------
__device__ __forceinline__ void mma16816(float* c, const uint32_t* a, const uint32_t* b) {
    asm volatile(
        "mma.sync.aligned.m16n8k16.row.col.f32.bf16.bf16.f32 "
        "{%0,%1,%2,%3}, {%4,%5,%6,%7}, {%8,%9}, {%0,%1,%2,%3};\n"
        : "+f"(c[0]), "+f"(c[1]), "+f"(c[2]), "+f"(c[3])
        : "r"(a[0]), "r"(a[1]), "r"(a[2]), "r"(a[3]), "r"(b[0]), "r"(b[1]));
}
__device__ __forceinline__ uint32_t bf2u(__nv_bfloat16 a, __nv_bfloat16 b) {
    __nv_bfloat162 v(a, b);
    return *reinterpret_cast<uint32_t*>(&v);
}
__device__ __forceinline__ uint32_t cvt2bf(float lo, float hi) {
    uint32_t r;
    asm("cvt.rn.bf16x2.f32 %0, %1, %2;" : "=r"(r) : "f"(hi), "f"(lo));
    return r;
}
__device__ __forceinline__ void cpa16(const void* smem, const void* gmem) {
    uint32_t s = (uint32_t)__cvta_generic_to_shared(smem);
    asm volatile("cp.async.cg.shared.global [%0], [%1], 16;\n" :: "r"(s), "l"(gmem));
}
#define CPA_COMMIT() asm volatile("cp.async.commit_group;\n" ::: "memory")
#define CPA_WAIT(N)  asm volatile("cp.async.wait_group %0;\n" :: "n"(N) : "memory")
__device__ __forceinline__ void ldsm4(uint32_t* r, uint32_t saddr) {
    asm volatile("ldmatrix.sync.aligned.m8n8.x4.shared.b16 {%0,%1,%2,%3}, [%4];"
        : "=r"(r[0]), "=r"(r[1]), "=r"(r[2]), "=r"(r[3]) : "r"(saddr));
}

// ---------------- PE tables --------------------------------------------------
__device__ __forceinline__ float pe_val(int ch, int h, int w, int c) {
    int blk = ch / c, t = ch - blk * c;
    int pos = (blk < 2) ? h : w;    // torch broadcast quirk
    int half = c >> 1;
    if (t < half) {
        float invf = powf(10000.f, -2.f * (float)t / (float)c);
        return sinf((float)pos * invf);
    } else {
        float invf = powf(10000.f, -2.f * (float)(t - half) / (float)c);
        return cosf((float)pos * invf);
    }
}
__global__ void k_petab() {
    int i = blockIdx.x * 256 + threadIdx.x;
    if (i < CY * 256) {
        int ch = i >> 8, n = i & 255;
        g_peY[i] = pe_val(ch, n >> 4, n & 15, 32);
    } else {
        int j = i - CY * 256;
        if (j < CS * 256) {
            int ch = j >> 8, n = j & 255;
            g_peS[j] = pe_val(ch, n >> 4, n & 15, 16);
        }
    }
}

// ---------------- weight prep: w3[co][ci][tap] -> bf16 h/l [tap][co][ci] ----
__global__ void k_wprep(const float* __restrict__ w3) {
    int j = blockIdx.x * 256 + threadIdx.x;
    if (j >= 27 * 96 * 96) return;
    int ci = j % 96, co = (j / 96) % 96, tap = j / 9216;
    float v = w3[(co * 96 + ci) * 27 + tap];
    __nv_bfloat16 h = __float2bfloat16(v);
    g_w3h[j] = h;
    g_w3l[j] = __float2bfloat16(v - __bfloat162float(h));
}

// ============================================================================
// PROJ: [0,128) proj_sv -> Vt bf16 | [128,256) proj_y1+QK
// ============================================================================
#define PROJ_SMEM 55552
__global__ __launch_bounds__(256) void k_proj(
    const float* __restrict__ Y, const float* __restrict__ S,
    const float* __restrict__ w_s, const float* __restrict__ b_s,
    const float* __restrict__ g_s, const float* __restrict__ be_s,
    const float* __restrict__ Wv,
    const float* __restrict__ w_y, const float* __restrict__ b_y,
    const float* __restrict__ g_y, const float* __restrict__ be_y,
    const float* __restrict__ Wq, const float* __restrict__ Wk)
{
    extern __shared__ __align__(16) float pool[];
    int bx = blockIdx.x, t = threadIdx.x;

    if (bx < 128) {
        int n0 = (bx & 63) * 64, b = bx >> 6;
        float* in_s = pool;            // [48][64], later reused as Vt staging
        float* wt   = pool + 3072;
        float* wv   = pool + 5376;
        float* s1   = pool + 7680;

        for (int i = t; i < CS * CS; i += 256) {
            int e = i % CS, c = i / CS;
            wt[i] = w_s[e * CS + c];
            wv[i] = Wv[i];
        }
        for (int i = t; i < CS * 64; i += 256) {
            int c = i >> 6, nl = i & 63;
            in_s[i] = S[(b * CS + c) * NN + n0 + nl]
                    + g_peS[c * 256 + ((n0 + nl) & 255)];
        }
        __syncthreads();

        int n = t & 63, eg = t >> 6;
        float acc[12];
#pragma unroll
        for (int k = 0; k < 12; k++) acc[k] = 0.f;
        for (int c = 0; c < CS; c++) {
            float x = in_s[c * 64 + n];
#pragma unroll
            for (int v = 0; v < 3; v++) {
                float4 w4 = *(const float4*)&wt[c * CS + eg * 12 + v * 4];
                acc[v*4+0] += w4.x * x; acc[v*4+1] += w4.y * x;
                acc[v*4+2] += w4.z * x; acc[v*4+3] += w4.w * x;
            }
        }
        float inv = rsqrtf(1.f + 1e-5f);
#pragma unroll
        for (int k = 0; k < 12; k++) {
            int e = eg * 12 + k;
            float y = (acc[k] + b_s[e]) * (g_s[e] * inv) + be_s[e];
            s1[n * 49 + e] = fmaxf(y, 0.f);
        }
        __syncthreads();

#pragma unroll
        for (int k = 0; k < 12; k++) acc[k] = 0.f;
        for (int d = 0; d < CS; d++) {
            float x = s1[n * 49 + d];
#pragma unroll
            for (int v = 0; v < 3; v++) {
                float4 w4 = *(const float4*)&wv[d * CS + eg * 12 + v * 4];
                acc[v*4+0] += w4.x * x; acc[v*4+1] += w4.y * x;
                acc[v*4+2] += w4.z * x; acc[v*4+3] += w4.w * x;
            }
        }
        // transpose V into in_s[d][n], then emit bf16 transposed global
        __syncthreads();           // everyone done reading in_s (inputs)
#pragma unroll
        for (int k = 0; k < 12; k++)
            in_s[(eg * 12 + k) * 64 + n] = acc[k];
        __syncthreads();
        for (int i = t; i < CS * 64; i += 256) {
            int d = i >> 6, nl = i & 63;
            g_Vth[(size_t)(b * CS + d) * NN + n0 + nl] = __float2bfloat16(in_s[i]);
        }
        return;
    }

    {   // proj_y1 + QK fused; Y1 lives only in smem. Q pre-scaled by QSC.
        int j = bx - 128;
        int n0 = (j & 63) * 64, b = j >> 6;
        float* in_s = pool;            // [96][64]
        float* wt   = pool + 6144;     // [c][e]
        float* s1   = pool + 10752;    // [n][49]

        for (int i = t; i < CY * CS; i += 256) {
            int e = i % CS, c = i / CS;
            wt[i] = w_y[e * CY + c];
        }
        for (int i = t; i < CY * 64; i += 256) {
            int c = i >> 6, nl = i & 63;
            in_s[i] = Y[(b * CY + c) * NN + n0 + nl]
                    + g_peY[c * 256 + ((n0 + nl) & 255)];
        }
        __syncthreads();

        int n = t & 63, eg = t >> 6;
        float acc[12];
#pragma unroll
        for (int k = 0; k < 12; k++) acc[k] = 0.f;
        for (int c = 0; c < CY; c++) {
            float x = in_s[c * 64 + n];
#pragma unroll
            for (int v = 0; v < 3; v++) {
                float4 w4 = *(const float4*)&wt[c * CS + eg * 12 + v * 4];
                acc[v*4+0] += w4.x * x; acc[v*4+1] += w4.y * x;
                acc[v*4+2] += w4.z * x; acc[v*4+3] += w4.w * x;
            }
        }
        float inv = rsqrtf(1.f + 1e-5f);
#pragma unroll
        for (int k = 0; k < 12; k++) {
            int e = eg * 12 + k;
            float y = (acc[k] + b_y[e]) * (g_y[e] * inv) + be_y[e];
            s1[n * 49 + e] = fmaxf(y, 0.f);
        }
        __syncthreads();

        float* wq = pool;
        float* wk = pool + 2304;
        for (int i = t; i < CS * CS; i += 256) { wq[i] = Wq[i]; wk[i] = Wk[i]; }
        __syncthreads();

        float aq[12], ak[12];
#pragma unroll
        for (int k = 0; k < 12; k++) { aq[k] = 0.f; ak[k] = 0.f; }
        for (int d = 0; d < CS; d++) {
            float x = s1[n * 49 + d];
#pragma unroll
            for (int v = 0; v < 3; v++) {
                float4 q4 = *(const float4*)&wq[d * CS + eg * 12 + v * 4];
                float4 k4 = *(const float4*)&wk[d * CS + eg * 12 + v * 4];
                aq[v*4+0] += q4.x * x; aq[v*4+1] += q4.y * x;
                aq[v*4+2] += q4.z * x; aq[v*4+3] += q4.w * x;
                ak[v*4+0] += k4.x * x; ak[v*4+1] += k4.y * x;
                ak[v*4+2] += k4.z * x; ak[v*4+3] += k4.w * x;
            }
        }
        int base = (b * NN + n0 + n) * CS + eg * 12;
#pragma unroll
        for (int k = 0; k < 12; k++) {
            g_Qh[base + k] = __float2bfloat16(aq[k] * QSC);
            g_Kh[base + k] = __float2bfloat16(ak[k]);
        }
    }
}

// ---------------- input prep: (Y + peY) -> channel-last padded bf16 h/l -----
__global__ __launch_bounds__(256) void k_ytrans(const float* __restrict__ Y) {
    int z = blockIdx.x, half = blockIdx.y, b = blockIdx.z, t = threadIdx.x;
    int y = t >> 4, x = t & 15;
    size_t dstbase = (((size_t)(b * 18 + z + 1) * 324) + (y + 1) * 18 + (x + 1)) * 96;
    uint32_t hp[24], lp[24];
#pragma unroll
    for (int c2 = 0; c2 < 24; c2++) {
        int ci = half * 48 + c2 * 2;
        float v0 = Y[(size_t)(b * CY + ci) * NN + z * 256 + t] + g_peY[ci * 256 + t];
        float v1 = Y[(size_t)(b * CY + ci + 1) * NN + z * 256 + t] + g_peY[(ci + 1) * 256 + t];
        __nv_bfloat16 h0 = __float2bfloat16(v0), h1 = __float2bfloat16(v1);
        hp[c2] = bf2u(h0, h1);
        lp[c2] = bf2u(__float2bfloat16(v0 - __bfloat162float(h0)),
                      __float2bfloat16(v1 - __bfloat162float(h1)));
    }
    uint4* dh = (uint4*)(g_Ypadh + dstbase + half * 48);
    uint4* dl = (uint4*)(g_Ypadl + dstbase + half * 48);
#pragma unroll
    for (int q = 0; q < 6; q++) {
        dh[q] = make_uint4(hp[q*4], hp[q*4+1], hp[q*4+2], hp[q*4+3]);
        dl[q] = make_uint4(lp[q*4], lp[q*4+1], lp[q*4+2], lp[q*4+3]);
    }
}

// ============================================================================
// Pass 1: column sums. A = K-tile persistent frags, B = Q chunks of 64.
// grid (32, 8, BB). smem 28672 B.
// ============================================================================
#define CS_SMEM 28672
__global__ __launch_bounds__(256) void k_colsum() {
    extern __shared__ __align__(16) unsigned char dsm[];
    __nv_bfloat16* KH = (__nv_bfloat16*)dsm;          // [128][56]
    __nv_bfloat16* QB = KH + 7168;                    // 2 bufs x QH[64][56]

    int k0 = blockIdx.x * 128, qq = blockIdx.y, b = blockIdx.z;
    int t = threadIdx.x, wid = t >> 5, l = t & 31;
    int lr = l >> 2, lc = (l & 3) * 2;
    int mb = wid * 16;

    {
        const __nv_bfloat16* s = g_Kh + (size_t)(b * NN + k0) * CS;
        for (int i = t; i < 768; i += 256) {
            int r = i / 6, c = i % 6;
            *(uint4*)(KH + r * 56 + c * 8) = *(const uint4*)(s + r * 48 + c * 8);
        }
    }
    __syncthreads();

    uint32_t kfh[3][4];
#pragma unroll
    for (int ks = 0; ks < 3; ks++) {
        int ko = ks * 16;
        kfh[ks][0] = *(uint32_t*)&KH[(mb + lr) * 56 + ko + lc];
        kfh[ks][1] = *(uint32_t*)&KH[(mb + 8 + lr) * 56 + ko + lc];
        kfh[ks][2] = *(uint32_t*)&KH[(mb + lr) * 56 + ko + lc + 8];
        kfh[ks][3] = *(uint32_t*)&KH[(mb + 8 + lr) * 56 + ko + lc + 8];
    }

    int lg = l >> 3, lrow = l & 7;
    int rowext = ((lg & 2) ? 8 : 0) + lrow;
    int colext = (lg & 1) ? 8 : 0;

    auto prefetchQ = [&](int ch, int bi) {
        int qb = qq * 512 + ch * 64;
        __nv_bfloat16* QH = QB + bi * 3584;
        const __nv_bfloat16* sh = g_Qh + (size_t)(b * NN + qb) * CS;
        for (int i = t; i < 384; i += 256) {
            int r = i / 6, c = i % 6;
            cpa16(QH + r * 56 + c * 8, sh + r * 48 + c * 8);
        }
        CPA_COMMIT();
    };

    float rs0 = 0.f, rs1 = 0.f;
    prefetchQ(0, 0);
    for (int ch = 0; ch < 8; ch++) {
        if (ch < 7) prefetchQ(ch + 1, (ch + 1) & 1);
        if (ch < 7) { CPA_WAIT(1); } else { CPA_WAIT(0); }
        __syncthreads();
        __nv_bfloat16* QH = QB + (ch & 1) * 3584;
        uint32_t qbase = (uint32_t)__cvta_generic_to_shared(QH);

#pragma unroll
        for (int nfp = 0; nfp < 4; nfp++) {
            float a0[4] = {0.f,0.f,0.f,0.f}, a1[4] = {0.f,0.f,0.f,0.f};
#pragma unroll
            for (int ks = 0; ks < 3; ks++) {
                int ko = ks * 16;
                uint32_t bf[4];
                ldsm4(bf, qbase + ((nfp * 16 + rowext) * 56 + ko + colext) * 2);
                mma16816(a0, kfh[ks], bf);
                mma16816(a1, kfh[ks], bf + 2);
            }
            rs0 += exp2f(a0[0]) + exp2f(a0[1]) + exp2f(a1[0]) + exp2f(a1[1]);
            rs1 += exp2f(a0[2]) + exp2f(a0[3]) + exp2f(a1[2]) + exp2f(a1[3]);
        }
        __syncthreads();
    }
    rs0 += __shfl_xor_sync(0xffffffffu, rs0, 1);
    rs0 += __shfl_xor_sync(0xffffffffu, rs0, 2);
    rs1 += __shfl_xor_sync(0xffffffffu, rs1, 1);
    rs1 += __shfl_xor_sync(0xffffffffu, rs1, 2);
    if ((l & 3) == 0) {
        g_psum[(b * 8 + qq) * NN + k0 + mb + lr]     = rs0;
        g_psum[(b * 8 + qq) * NN + k0 + mb + 8 + lr] = rs1;
    }
}

// ---------------- iz: 1 / (sum of 8 psum partials) --------------------------
__global__ void k_iz() {
    int k = blockIdx.x * 256 + threadIdx.x, b = blockIdx.y;
    float s = 0.f;
#pragma unroll
    for (int i = 0; i < 8; i++) s += g_psum[(b * 8 + i) * NN + k];
    g_iz[b * NN + k] = 1.f / s;
}

// ============================================================================
// flash pass2: QK recompute -> exp2 * iz[k] -> P as A-frags into 1-term P @ V.
// grid (32, 8, BB). smem 28672 B.
// ============================================================================
#define FLASH_SMEM 28672
__global__ __launch_bounds__(256) void k_flash() {
    extern __shared__ __align__(16) unsigned char dsm[];
    __nv_bfloat16* base = (__nv_bfloat16*)dsm;
    __nv_bfloat16* KB = base;                 // 2 bufs x KH[64][56]; overlaps Q staging
    __nv_bfloat16* VB = base + 7168;          // 2 bufs x VH[48][72]
    float* IZB = (float*)(base + 14080);      // 2 bufs x 64 floats

    int qblk = blockIdx.x, kq = blockIdx.y, b = blockIdx.z;
    int t = threadIdx.x, wid = t >> 5, l = t & 31;
    int lr = l >> 2, lc = (l & 3) * 2;
    int q0 = qblk * 128, mb = wid * 16;

    {
        __nv_bfloat16* QH = base;
        const __nv_bfloat16* s = g_Qh + (size_t)(b * NN + q0) * CS;
        for (int i = t; i < 768; i += 256) {
            int r = i / 6, c = i % 6;
            *(uint4*)(QH + r * 56 + c * 8) = *(const uint4*)(s + r * 48 + c * 8);
        }
    }
    __syncthreads();

    uint32_t qfh[3][4];
    {
        __nv_bfloat16* QH = base;
#pragma unroll
        for (int ks = 0; ks < 3; ks++) {
            int ko = ks * 16;
            qfh[ks][0] = *(uint32_t*)&QH[(mb + lr) * 56 + ko + lc];
            qfh[ks][1] = *(uint32_t*)&QH[(mb + 8 + lr) * 56 + ko + lc];
            qfh[ks][2] = *(uint32_t*)&QH[(mb + lr) * 56 + ko + lc + 8];
            qfh[ks][3] = *(uint32_t*)&QH[(mb + 8 + lr) * 56 + ko + lc + 8];
        }
    }
    __syncthreads();   // frag extraction done before K bufs overwrite Q region

    int lg = l >> 3, lrow = l & 7;
    int rowext = ((lg & 2) ? 8 : 0) + lrow;
    int colext = (lg & 1) ? 8 : 0;

    auto prefetchKV = [&](int ch, int bi) {
        int kb = kq * 512 + ch * 64;
        __nv_bfloat16* KHc = KB + bi * 3584;
        __nv_bfloat16* VHc = VB + bi * 3456;
        const __nv_bfloat16* skh = g_Kh + (size_t)(b * NN + kb) * CS;
        for (int i = t; i < 384; i += 256) {
            int r = i / 6, c = i % 6;
            cpa16(KHc + r * 56 + c * 8, skh + r * 48 + c * 8);
        }
        const __nv_bfloat16* svh = g_Vth + (size_t)(b * CS) * NN + kb;
        for (int i = t; i < 384; i += 256) {
            int r = i / 8, c = i % 8;
            cpa16(VHc + r * 72 + c * 8, svh + (size_t)r * NN + c * 8);
        }
        if (t < 16)
            cpa16(IZB + bi * 64 + t * 4, g_iz + b * NN + kb + t * 4);
        CPA_COMMIT();
    };

    float pv[6][4];
#pragma unroll
    for (int nv = 0; nv < 6; nv++)
#pragma unroll
        for (int c = 0; c < 4; c++) pv[nv][c] = 0.f;

    prefetchKV(0, 0);
    for (int ch = 0; ch < 8; ch++) {
        if (ch < 7) prefetchKV(ch + 1, (ch + 1) & 1);
        if (ch < 7) { CPA_WAIT(1); } else { CPA_WAIT(0); }
        __syncthreads();
        __nv_bfloat16* KHc = KB + (ch & 1) * 3584;
        __nv_bfloat16* VHc = VB + (ch & 1) * 3456;
        const float* IZc = IZB + (ch & 1) * 64;
        uint32_t kbase = (uint32_t)__cvta_generic_to_shared(KHc);
        uint32_t vhb   = (uint32_t)__cvta_generic_to_shared(VHc);

#pragma unroll
        for (int nfp = 0; nfp < 4; nfp++) {
            float a0[4] = {0.f,0.f,0.f,0.f}, a1[4] = {0.f,0.f,0.f,0.f};
#pragma unroll
            for (int ks = 0; ks < 3; ks++) {
                int ko = ks * 16;
                uint32_t bf[4];
                ldsm4(bf, kbase + ((nfp * 16 + rowext) * 56 + ko + colext) * 2);
                mma16816(a0, qfh[ks], bf);
                mma16816(a1, qfh[ks], bf + 2);
            }
            int kop = nfp * 16;
            float z0 = IZc[kop + lc],     z1 = IZc[kop + lc + 1];
            float z2 = IZc[kop + 8 + lc], z3 = IZc[kop + 8 + lc + 1];
            uint32_t ph[4];
            ph[0] = cvt2bf(exp2f(a0[0]) * z0, exp2f(a0[1]) * z1);
            ph[1] = cvt2bf(exp2f(a0[2]) * z0, exp2f(a0[3]) * z1);
            ph[2] = cvt2bf(exp2f(a1[0]) * z2, exp2f(a1[1]) * z3);
            ph[3] = cvt2bf(exp2f(a1[2]) * z2, exp2f(a1[3]) * z3);
#pragma unroll
            for (int p2 = 0; p2 < 3; p2++) {
                uint32_t vh[4];
                uint32_t off = ((p2 * 16 + rowext) * 72 + kop + colext) * 2;
                ldsm4(vh, vhb + off);
                mma16816(pv[2*p2],     ph, vh);
                mma16816(pv[2*p2 + 1], ph, vh + 2);
            }
        }
        __syncthreads();
    }

#pragma unroll
    for (int nv = 0; nv < 6; nv++) {
        int r = q0 + mb + lr, col = nv * 8 + lc;
        float* basep = &g_Xp[((size_t)(kq * BB + b) * NN + r) * CS + col];
        *(float2*)basep = make_float2(pv[nv][0], pv[nv][1]);
        *(float2*)(basep + 8 * CS) = make_float2(pv[nv][2], pv[nv][3]);
    }
}

// ============================================================================
// conv3d implicit GEMM, 3-term bf16. grid (16 z, 6 = dz*2+cihalf, BB).
// Full 324-row slab + per-tap weight tiles staged via cp.async (double-buffered)
// -> A-frags via ldsm (no scattered LDG). smem 62208 + 36864 = 99072 B, occ 1.
// ============================================================================
#define CONV_SMEM 99072
__global__ __launch_bounds__(256) void k_conv() {
    extern __shared__ __align__(16) unsigned char dsm[];
    __nv_bfloat16* SH = (__nv_bfloat16*)dsm;      // [324][48] hi
    __nv_bfloat16* SL = SH + 324 * 48;            // [324][48] lo
    __nv_bfloat16* WB = SL + 324 * 48;            // 2 bufs x (WH[96][48] + WL[96][48])

    int z = blockIdx.x, s = blockIdx.y, b = blockIdx.z;
    int dz = s >> 1, half = s & 1;
    int t = threadIdx.x, wid = t >> 5, l = t & 31;
    int wm = wid >> 2, wn = wid & 3;              // 2 m-warps x 4 n-warps
    int lg = l >> 3, lrow = l & 7;
    // B (input) ldsm pattern
    int rowext = ((lg & 2) ? 8 : 0) + lrow;
    int colext = (lg & 1) ? 8 : 0;
    // A (weight) ldsm pattern: r0=(r,k) r1=(r+8,k) r2=(r,k+8) r3=(r+8,k+8)
    int rowA = ((lg & 1) ? 8 : 0) + lrow;
    int colA = (lg & 2) ? 8 : 0;

    // stage weight tile for tap (0..8) into buffer bi
    auto stageW = [&](int tap, int bi) {
        int tapg = dz * 9 + tap;
        __nv_bfloat16* WH = WB + bi * 9216;
        __nv_bfloat16* WL = WH + 4608;
        const __nv_bfloat16* sh = g_w3h + (size_t)tapg * 9216 + half * 48;
        const __nv_bfloat16* sl = g_w3l + (size_t)tapg * 9216 + half * 48;
        for (int i = t; i < 576; i += 256) {
            int r = i / 6, c = i % 6;
            cpa16(WH + r * 48 + c * 8, sh + (size_t)r * 96 + c * 8);
            cpa16(WL + r * 48 + c * 8, sl + (size_t)r * 96 + c * 8);
        }
        CPA_COMMIT();
    };

    // group 0: input slab + weights tap 0
    {
        const __nv_bfloat16* srch = g_Ypadh + ((size_t)(b * 18 + z + dz) * 324) * 96 + half * 48;
        const __nv_bfloat16* srcl = g_Ypadl + ((size_t)(b * 18 + z + dz) * 324) * 96 + half * 48;
        for (int i = t; i < 324 * 6; i += 256) {
            int r = i / 6, c = i % 6;
            cpa16(SH + r * 48 + c * 8, srch + (size_t)r * 96 + c * 8);
            cpa16(SL + r * 48 + c * 8, srcl + (size_t)r * 96 + c * 8);
        }
    }
    stageW(0, 0);   // commits group 0 (slab + w0)

    int py[4], px[4];
#pragma unroll
    for (int pair = 0; pair < 4; pair++) {
        int n = wn * 64 + pair * 16 + rowext;
        py[pair] = n >> 4;
        px[pair] = n & 15;
    }
    uint32_t sbh = (uint32_t)__cvta_generic_to_shared(SH);
    uint32_t sbl = (uint32_t)__cvta_generic_to_shared(SL);

    float acc[3][8][4];
#pragma unroll
    for (int mf = 0; mf < 3; mf++)
#pragma unroll
        for (int nf = 0; nf < 8; nf++)
#pragma unroll
            for (int c = 0; c < 4; c++) acc[mf][nf][c] = 0.f;

    for (int tap = 0; tap < 9; tap++) {
        if (tap < 8) stageW(tap + 1, (tap + 1) & 1);
        if (tap < 8) { CPA_WAIT(1); } else { CPA_WAIT(0); }
        __syncthreads();
        int dy = tap / 3, dx = tap % 3;
        __nv_bfloat16* WH = WB + (tap & 1) * 9216;
        __nv_bfloat16* WL = WH + 4608;
        uint32_t wbh = (uint32_t)__cvta_generic_to_shared(WH);
        uint32_t wbl = (uint32_t)__cvta_generic_to_shared(WL);

#pragma unroll
        for (int ks = 0; ks < 3; ks++) {
            uint32_t ah[3][4], al[3][4];
#pragma unroll
            for (int mf = 0; mf < 3; mf++) {
                uint32_t aoff = (uint32_t)((wm * 48 + mf * 16 + rowA) * 48
                                           + ks * 16 + colA) * 2;
                ldsm4(ah[mf], wbh + aoff);
                ldsm4(al[mf], wbl + aoff);
            }
            uint32_t bh[4][4], bl[4][4];
#pragma unroll
            for (int pair = 0; pair < 4; pair++) {
                int srow = (py[pair] + dy) * 18 + px[pair] + dx;
                uint32_t off = (uint32_t)(srow * 48 + ks * 16 + colext) * 2;
                ldsm4(bh[pair], sbh + off);
                ldsm4(bl[pair], sbl + off);
            }
#pragma unroll
            for (int mf = 0; mf < 3; mf++)
#pragma unroll
                for (int pair = 0; pair < 4; pair++) {
                    mma16816(acc[mf][2*pair],     ah[mf], bh[pair]);
                    mma16816(acc[mf][2*pair],     al[mf], bh[pair]);
                    mma16816(acc[mf][2*pair],     ah[mf], bl[pair]);
                    mma16816(acc[mf][2*pair + 1], ah[mf], bh[pair] + 2);
                    mma16816(acc[mf][2*pair + 1], al[mf], bh[pair] + 2);
                    mma16816(acc[mf][2*pair + 1], ah[mf], bl[pair] + 2);
                }
        }
        __syncthreads();
    }

    float* out = g_Y3p + (size_t)s * (BB * CY * NN) + (size_t)(b * CY) * NN + z * 256;
#pragma unroll
    for (int mf = 0; mf < 3; mf++) {
        int r0 = wm * 48 + mf * 16 + (l >> 2);
#pragma unroll
        for (int nf = 0; nf < 8; nf++) {
            int c = wn * 64 + nf * 8 + (l & 3) * 2;
            *(float2*)&out[(size_t)r0 * NN + c]       = make_float2(acc[mf][nf][0], acc[mf][nf][1]);
            *(float2*)&out[(size_t)(r0 + 8) * NN + c] = make_float2(acc[mf][nf][2], acc[mf][nf][3]);
        }
    }
}

// ============================================================================
// FUSE2: [0,128) zout | [128,256) y2out (sums 6 conv partials)
// ============================================================================
#define FUSE2_SMEM 43008
__global__ __launch_bounds__(256) void k_fuse2(
    const float* __restrict__ S,
    const float* __restrict__ w_o, const float* __restrict__ b_o,
    const float* __restrict__ g_o, const float* __restrict__ be_o,
    const float* __restrict__ w_y2, const float* __restrict__ b_y2,
    const float* __restrict__ g_y2, const float* __restrict__ be_y2,
    const float* __restrict__ b3, float* __restrict__ out)
{
    extern __shared__ __align__(16) float pool[];
    int bx = blockIdx.x, t = threadIdx.x;

    if (bx < 128) {
        int n0 = (bx & 63) * 64, b = bx >> 6;
        float* xs  = pool;
        float* wot = pool + 3072;

        for (int i = t; i < CS * CS; i += 256) {
            int e = i % CS, d = i / CS;
            wot[i] = w_o[e * CS + d];
        }
        {
            int n = t & 63, v = t >> 6;
            const size_t cstride = (size_t)BB * NN * CS;
            const float* src = g_Xp + (size_t)(b * NN + n0 + n) * CS;
#pragma unroll
            for (int r = 0; r < 3; r++) {
                int dv = v + r * 4;
                float4 x = *(const float4*)&src[dv * 4];
#pragma unroll
                for (int p = 1; p < 8; p++) {
                    float4 xp = *(const float4*)&src[p * cstride + dv * 4];
                    x.x += xp.x; x.y += xp.y; x.z += xp.z; x.w += xp.w;
                }
                xs[(dv*4+0)*64+n] = x.x; xs[(dv*4+1)*64+n] = x.y;
                xs[(dv*4+2)*64+n] = x.z; xs[(dv*4+3)*64+n] = x.w;
            }
        }
        __syncthreads();

        int n = t & 63, eg = t >> 6;
        float acc[12];
#pragma unroll
        for (int k = 0; k < 12; k++) acc[k] = 0.f;
        for (int d = 0; d < CS; d++) {
            float x = xs[d * 64 + n];
#pragma unroll
            for (int v = 0; v < 3; v++) {
                float4 w4 = *(const float4*)&wot[d * CS + eg * 12 + v * 4];
                acc[v*4+0] += w4.x * x; acc[v*4+1] += w4.y * x;
                acc[v*4+2] += w4.z * x; acc[v*4+3] += w4.w * x;
            }
        }
        float inv = rsqrtf(1.f + 1e-5f);
#pragma unroll
        for (int k = 0; k < 12; k++) {
            int e = eg * 12 + k;
            float y = (acc[k] + b_o[e]) * (g_o[e] * inv) + be_o[e];
            y = fmaxf(y, 0.f);
            float spe = S[(b * CS + e) * NN + n0 + n]
                      + g_peS[e * 256 + ((n0 + n) & 255)];
            out[(b * 96 + e) * NN + n0 + n] = y * spe;
        }
        return;
    }

    {
        int j = bx - 128;
        int n0 = (j & 63) * 64, b = j >> 6;
        float* in_s = pool;
        float* wt   = pool + 6144;

        for (int i = t; i < CY * CS; i += 256) {
            int e = i % CS, c = i / CS;
            wt[i] = w_y2[e * CY + c];
        }
        const size_t pstride = (size_t)BB * CY * NN;
        const float* src = g_Y3p + (size_t)(b * CY) * NN + n0;
        for (int i = t; i < CY * 64; i += 256) {
            int c = i >> 6, n = i & 63;
            float v = b3[c];
#pragma unroll
            for (int p = 0; p < 6; p++) v += src[p * pstride + c * NN + n];
            in_s[i] = v;
        }
        __syncthreads();

        int n = t & 63, eg = t >> 6;
        float acc[12];
#pragma unroll
        for (int k = 0; k < 12; k++) acc[k] = 0.f;
        for (int c = 0; c < CY; c++) {
            float x = in_s[c * 64 + n];
#pragma unroll
            for (int v = 0; v < 3; v++) {
                float4 w4 = *(const float4*)&wt[c * CS + eg * 12 + v * 4];
                acc[v*4+0] += w4.x * x; acc[v*4+1] += w4.y * x;
                acc[v*4+2] += w4.z * x; acc[v*4+3] += w4.w * x;
            }
        }
        float inv = rsqrtf(1.f + 1e-5f);
#pragma unroll
        for (int k = 0; k < 12; k++) {
            int e = eg * 12 + k;
            float y = (acc[k] + b_y2[e]) * (g_y2[e] * inv) + be_y2[e];
            out[(b * 96 + 48 + e) * NN + n0 + n] = fmaxf(y, 0.f);
        }
    }
}

// ---------------- launch -----------------------------------------------------
extern "C" void kernel_launch(void* const* d_in, const int* in_sizes, int n_in,
                              void* d_out, int out_size)
{
    const float* Y    = (const float*)d_in[0];
    const float* S    = (const float*)d_in[1];
    const float* w_s  = (const float*)d_in[2];
    const float* b_s  = (const float*)d_in[3];
    const float* g_s  = (const float*)d_in[4];
    const float* be_s = (const float*)d_in[5];
    const float* w_y  = (const float*)d_in[6];
    const float* b_y  = (const float*)d_in[7];
    const float* g_y  = (const float*)d_in[8];
    const float* be_y = (const float*)d_in[9];
    const float* Wq   = (const float*)d_in[10];
    const float* Wk   = (const float*)d_in[11];
    const float* Wv   = (const float*)d_in[12];
    const float* w_o  = (const float*)d_in[13];
    const float* b_o  = (const float*)d_in[14];
    const float* g_o  = (const float*)d_in[15];
    const float* be_o = (const float*)d_in[16];
    const float* w3   = (const float*)d_in[17];
    const float* b3   = (const float*)d_in[18];
    const float* w_y2 = (const float*)d_in[19];
    const float* b_y2 = (const float*)d_in[20];
    const float* g_y2 = (const float*)d_in[21];
    const float* be_y2= (const float*)d_in[22];
    float* out = (float*)d_out;

    static cudaStream_t s2 = nullptr;
    static cudaEvent_t evP = nullptr, ev2 = nullptr;
    static int attr_done = 0;
    if (!attr_done) {
        cudaFuncSetAttribute(k_proj,   cudaFuncAttributeMaxDynamicSharedMemorySize, PROJ_SMEM);
        cudaFuncSetAttribute(k_colsum, cudaFuncAttributeMaxDynamicSharedMemorySize, CS_SMEM);
        cudaFuncSetAttribute(k_flash,  cudaFuncAttributeMaxDynamicSharedMemorySize, FLASH_SMEM);
        cudaFuncSetAttribute(k_conv,   cudaFuncAttributeMaxDynamicSharedMemorySize, CONV_SMEM);
        cudaStreamCreateWithFlags(&s2, cudaStreamNonBlocking);
        cudaEventCreateWithFlags(&evP, cudaEventDisableTiming);
        cudaEventCreateWithFlags(&ev2, cudaEventDisableTiming);
        attr_done = 1;
    }

    // s2: weight prep needs nothing
    k_wprep <<<972, 256, 0, s2>>>(w3);
    // default: PE tables; conv branch forks right after (needs only peY + Y)
    k_petab <<<144, 256>>>();
    cudaEventRecord(evP, 0);
    cudaStreamWaitEvent(s2, evP, 0);
    k_ytrans<<<dim3(16, 2, BB), 256, 0, s2>>>(Y);
    k_conv  <<<dim3(16, 6, BB), 256, CONV_SMEM, s2>>>();
    cudaEventRecord(ev2, s2);

    // attention chain on default
    k_proj  <<<256, 256, PROJ_SMEM>>>(Y, S, w_s, b_s, g_s, be_s, Wv,
                                      w_y, b_y, g_y, be_y, Wq, Wk);
    k_colsum<<<dim3(32, 8, BB), 256, CS_SMEM>>>();
    k_iz    <<<dim3(16, BB), 256>>>();
    k_flash <<<dim3(32, 8, BB), 256, FLASH_SMEM>>>();

    cudaStreamWaitEvent(0, ev2, 0);
    k_fuse2 <<<256, 256, FUSE2_SMEM>>>(S, w_o, b_o, g_o, be_o,
                                       w_y2, b_y2, g_y2, be_y2, b3, out);
}